// round 11
// baseline (speedup 1.0000x reference)
#include <cuda_runtime.h>
#include <cstddef>

typedef unsigned long long u64;

// Problem constants
#define B_   8192
#define T_   2048
#define H_   51
#define HP   52            // padded hidden
#define GP   208           // 4*HP padded gate columns
#define BB   64            // batch rows per block
#define BH   32            // batch rows per half
#define NTH  256           // threads per block (two 128-thread halves)
#define NBLK (B_ / BB)     // 128 blocks

#define GPITCH 66          // gsm pair-row pitch (floats): 33 u64 -> conflict-free STS.64
#define NPAIR  (GP / 2)    // 104 column pairs

// Shared memory layout (float offsets)
#define OFF_W1   0                          // [HP][GP]    h1 -> gates1 (k-major)
#define OFF_W2   (OFF_W1 + HP * GP)         // [2*HP][GP]  [h1;h2] -> gates2
#define OFF_WX   (OFF_W2 + 2 * HP * GP)     // [GP]
#define OFF_BS1  (OFF_WX + GP)              // [GP]
#define OFF_BS2  (OFF_BS1 + GP)             // [GP]
#define OFF_WLIN (OFF_BS2 + GP)             // [64]
#define OFF_XS   (OFF_WLIN + 64)            // [64]  (32 per half)
#define OFF_HCAT (OFF_XS + 64)              // per half: [2*HP][BH]
#define HCAT_HALF (2 * HP * BH)
#define OFF_GSM  (OFF_HCAT + 2 * HCAT_HALF) // per half: [NPAIR][GPITCH]
#define GSM_HALF (NPAIR * GPITCH)
#define SMEM_FLOATS (OFF_GSM + 2 * GSM_HALF)
#define SMEM_BYTES  (SMEM_FLOATS * (int)sizeof(float))   // ~214.4 KB

__device__ __forceinline__ float sigf(float v) {
    return __fdividef(1.0f, 1.0f + __expf(-v));
}
__device__ __forceinline__ float tanhfast(float v) {
    return __fdividef(2.0f, 1.0f + __expf(-2.0f * v)) - 1.0f;
}

__device__ __forceinline__ u64 pack2(float lo, float hi) {
    u64 r; asm("mov.b64 %0, {%1, %2};" : "=l"(r) : "f"(lo), "f"(hi)); return r;
}
__device__ __forceinline__ u64 fma2(u64 a, u64 b, u64 c) {
    u64 d; asm("fma.rn.f32x2 %0, %1, %2, %3;" : "=l"(d) : "l"(a), "l"(b), "l"(c)); return d;
}
__device__ __forceinline__ u64 add2(u64 a, u64 b) {
    u64 d; asm("add.rn.f32x2 %0, %1, %2;" : "=l"(d) : "l"(a), "l"(b)); return d;
}

__device__ __forceinline__ void half_bar(int half) {
    asm volatile("bar.sync %0, 128;" :: "r"(half + 1) : "memory");
}

// Register-tiled packed GEMM over one half:
// acc{A,B}[13] (f32x2 over col pairs) += hcat(K x 32) * W(K x 208)
// Thread tile: batch rows (b0, b0+1), cols j0..j0+25 as 13 pairs.
template <int K>
__device__ __forceinline__ void gemm_tile2(const float* __restrict__ W,
                                           const float* __restrict__ hc,
                                           int b0, int j0,
                                           u64 accA[13], u64 accB[13]) {
#pragma unroll
    for (int c = 0; c < 13; c++) { accA[c] = 0ull; accB[c] = 0ull; }
#pragma unroll 4
    for (int k = 0; k < K; k++) {
        float2 hv = *reinterpret_cast<const float2*>(hc + k * BH + b0);
        u64 ha = pack2(hv.x, hv.x);
        u64 hb = pack2(hv.y, hv.y);
        const u64* wr = reinterpret_cast<const u64*>(W + k * GP + j0);
#pragma unroll
        for (int c = 0; c < 13; c++) {
            u64 w = wr[c];
            accA[c] = fma2(ha, w, accA[c]);
            accB[c] = fma2(hb, w, accB[c]);
        }
    }
}

extern __shared__ float smf[];

__global__ __launch_bounds__(NTH, 1)
void lstm_rnn_kernel(const float* __restrict__ x,
                     const float* __restrict__ Wih1, const float* __restrict__ Whh1,
                     const float* __restrict__ bih1, const float* __restrict__ bhh1,
                     const float* __restrict__ Wih2, const float* __restrict__ Whh2,
                     const float* __restrict__ bih2, const float* __restrict__ bhh2,
                     const float* __restrict__ Wlin, const float* __restrict__ blin_p,
                     float* __restrict__ out) {
    float* W1   = smf + OFF_W1;
    float* W2   = smf + OFF_W2;
    float* wx   = smf + OFF_WX;
    float* bs1  = smf + OFF_BS1;
    float* bs2  = smf + OFF_BS2;
    float* wlin = smf + OFF_WLIN;

    const int t    = threadIdx.x;
    const int half = t >> 7;          // 0 or 1
    const int tl   = t & 127;         // lane within half
    const int bbase = blockIdx.x * BB + half * BH;

    float* xs   = smf + OFF_XS   + half * BH;
    float* hcat = smf + OFF_HCAT + half * HCAT_HALF;
    float* gsm  = smf + OFF_GSM  + half * GSM_HALF;

    // ---- one-time init: transpose + pad weights into SMEM (all 256 threads) ----
    for (int idx = t; idx < HP * GP; idx += NTH) {
        int k = idx / GP, gp = idx % GP;
        int g = gp / HP, j = gp % HP;
        W1[idx] = (j < H_ && k < H_) ? Whh1[(g * H_ + j) * H_ + k] : 0.f;
    }
    for (int idx = t; idx < 2 * HP * GP; idx += NTH) {
        int k = idx / GP, gp = idx % GP;
        int g = gp / HP, j = gp % HP;
        float v = 0.f;
        if (j < H_) {
            if (k < H_)                      v = Wih2[(g * H_ + j) * H_ + k];
            else if (k >= HP && k < HP + H_) v = Whh2[(g * H_ + j) * H_ + (k - HP)];
        }
        W2[idx] = v;
    }
    for (int gp = t; gp < GP; gp += NTH) {
        int g = gp / HP, j = gp % HP;
        if (j < H_) {
            wx[gp]  = Wih1[g * H_ + j];
            bs1[gp] = bih1[g * H_ + j] + bhh1[g * H_ + j];
            bs2[gp] = bih2[g * H_ + j] + bhh2[g * H_ + j];
        } else {
            wx[gp] = 0.f; bs1[gp] = 0.f; bs2[gp] = 0.f;
        }
    }
    if (t < 64) wlin[t] = (t < H_) ? Wlin[t] : 0.f;
    for (int idx = t; idx < 2 * HCAT_HALF; idx += NTH) (smf + OFF_HCAT)[idx] = 0.f;
    const float blin = blin_p[0];

    // GEMM tile coordinates (per half)
    const int bg = tl >> 3;            // 0..15
    const int b0 = bg * 2;             // batch rows b0, b0+1
    const int j0 = (tl & 7) * 26;      // 13 col pairs starting at j0 (even)
    const int p0 = j0 >> 1;

    // Elementwise coordinates (per half): thread owns batch row `be`, j = jb + 4i
    const int be = tl & 31;
    const int jb = tl >> 5;            // 0..3

    float c1r[13], c2r[13];
#pragma unroll
    for (int i = 0; i < 13; i++) { c1r[i] = 0.f; c2r[i] = 0.f; }

    float xnext = (tl < BH) ? x[(size_t)(bbase + tl) * T_] : 0.f;

    __syncthreads();

    for (int step = 0; step < T_; ++step) {
        if (tl < BH) xs[tl] = xnext;
        half_bar(half);
        if (tl < BH && step + 1 < T_)
            xnext = __ldg(&x[(size_t)(bbase + tl) * T_ + step + 1]);

        // ---- layer-1 GEMM: gates1 = h1 @ Whh1^T (+ x*wx + bias) ----
        {
            u64 accA[13], accB[13];
            gemm_tile2<HP>(W1, hcat, b0, j0, accA, accB);
            u64 xA = pack2(xs[b0], xs[b0]);
            u64 xB = pack2(xs[b0 + 1], xs[b0 + 1]);
#pragma unroll
            for (int c = 0; c < 13; c++) {
                int gp = j0 + 2 * c;
                u64 bp  = *reinterpret_cast<const u64*>(bs1 + gp);
                u64 wxp = *reinterpret_cast<const u64*>(wx + gp);
                u64 vA = fma2(xA, wxp, add2(accA[c], bp));
                u64 vB = fma2(xB, wxp, add2(accB[c], bp));
                float* row = gsm + (p0 + c) * GPITCH;
                *reinterpret_cast<u64*>(row + b0 * 2)       = vA;
                *reinterpret_cast<u64*>(row + (b0 + 1) * 2) = vB;
            }
        }
        half_bar(half);

        // ---- layer-1 elementwise (h1 -> hcat rows 0..51) ----
#pragma unroll
        for (int i = 0; i < 13; i++) {
            int j = jb + 4 * i;
            int g0 = (0 * HP + j), g1 = (1 * HP + j), g2 = (2 * HP + j), g3 = (3 * HP + j);
            float ig = gsm[(g0 >> 1) * GPITCH + be * 2 + (g0 & 1)];
            float fg = gsm[(g1 >> 1) * GPITCH + be * 2 + (g1 & 1)];
            float gg = gsm[(g2 >> 1) * GPITCH + be * 2 + (g2 & 1)];
            float og = gsm[(g3 >> 1) * GPITCH + be * 2 + (g3 & 1)];
            float ia = sigf(ig), fa = sigf(fg), ga = tanhfast(gg), oa = sigf(og);
            float c = fmaf(fa, c1r[i], ia * ga);
            c1r[i] = c;
            hcat[j * BH + be] = oa * tanhfast(c);
        }
        half_bar(half);

        // ---- layer-2 GEMM: gates2 = [h1;h2] @ [Wih2;Whh2]^T (+ bias) ----
        {
            u64 accA[13], accB[13];
            gemm_tile2<2 * HP>(W2, hcat, b0, j0, accA, accB);
#pragma unroll
            for (int c = 0; c < 13; c++) {
                int gp = j0 + 2 * c;
                u64 bp = *reinterpret_cast<const u64*>(bs2 + gp);
                float* row = gsm + (p0 + c) * GPITCH;
                *reinterpret_cast<u64*>(row + b0 * 2)       = add2(accA[c], bp);
                *reinterpret_cast<u64*>(row + (b0 + 1) * 2) = add2(accB[c], bp);
            }
        }
        half_bar(half);

        // ---- layer-2 elementwise (h2 -> hcat rows 52..103) ----
#pragma unroll
        for (int i = 0; i < 13; i++) {
            int j = jb + 4 * i;
            int g0 = (0 * HP + j), g1 = (1 * HP + j), g2 = (2 * HP + j), g3 = (3 * HP + j);
            float ig = gsm[(g0 >> 1) * GPITCH + be * 2 + (g0 & 1)];
            float fg = gsm[(g1 >> 1) * GPITCH + be * 2 + (g1 & 1)];
            float gg = gsm[(g2 >> 1) * GPITCH + be * 2 + (g2 & 1)];
            float og = gsm[(g3 >> 1) * GPITCH + be * 2 + (g3 & 1)];
            float ia = sigf(ig), fa = sigf(fg), ga = tanhfast(gg), oa = sigf(og);
            float c = fmaf(fa, c2r[i], ia * ga);
            c2r[i] = c;
            hcat[(HP + j) * BH + be] = oa * tanhfast(c);
        }
        half_bar(half);

        // ---- output projection: y[b] = h2 . Wlin + blin ----
        if (tl < BH) {
            float y = blin;
#pragma unroll
            for (int j = 0; j < H_; j++)
                y = fmaf(hcat[(HP + j) * BH + tl], wlin[j], y);
            out[(size_t)(bbase + tl) * T_ + step] = y;
        }
        // loop-top half_bar separates out-proj hcat reads from next write phases
    }
}

extern "C" void kernel_launch(void* const* d_in, const int* in_sizes, int n_in,
                              void* d_out, int out_size) {
    (void)in_sizes; (void)n_in; (void)out_size;
    const float* x    = (const float*)d_in[0];
    const float* Wih1 = (const float*)d_in[1];
    const float* Whh1 = (const float*)d_in[2];
    const float* bih1 = (const float*)d_in[3];
    const float* bhh1 = (const float*)d_in[4];
    const float* Wih2 = (const float*)d_in[5];
    const float* Whh2 = (const float*)d_in[6];
    const float* bih2 = (const float*)d_in[7];
    const float* bhh2 = (const float*)d_in[8];
    const float* Wlin = (const float*)d_in[9];
    const float* blin = (const float*)d_in[10];
    float* out = (float*)d_out;

    cudaFuncSetAttribute(lstm_rnn_kernel,
                         cudaFuncAttributeMaxDynamicSharedMemorySize, SMEM_BYTES);

    lstm_rnn_kernel<<<NBLK, NTH, SMEM_BYTES>>>(x, Wih1, Whh1, bih1, bhh1,
                                               Wih2, Whh2, bih2, bhh2,
                                               Wlin, blin, out);
}

// round 12
// speedup vs baseline: 1.0021x; 1.0021x over previous
#include <cuda_runtime.h>
#include <cstddef>

typedef unsigned long long u64;

// Problem constants
#define B_   8192
#define T_   2048
#define H_   51
#define HP   52            // padded hidden
#define GP   208           // 4*HP padded gate columns
#define BB   64            // batch rows per block
#define BH   32            // batch rows per half
#define NTH  256           // threads per block (two 128-thread halves)
#define NBLK (B_ / BB)     // 128 blocks

#define GPITCH 66          // gsm pair-row pitch (floats): 33 u64 -> conflict-free STS.64
#define NPAIR  (GP / 2)    // 104 column pairs

// Shared memory layout (float offsets)
#define OFF_W1   0                          // [HP][GP]    h1 -> gates1 (k-major)
#define OFF_W2   (OFF_W1 + HP * GP)         // [2*HP][GP]  [h1;h2] -> gates2
#define OFF_WX   (OFF_W2 + 2 * HP * GP)     // [GP]
#define OFF_BS1  (OFF_WX + GP)              // [GP]
#define OFF_BS2  (OFF_BS1 + GP)             // [GP]
#define OFF_WLIN (OFF_BS2 + GP)             // [64]
#define OFF_XS   (OFF_WLIN + 64)            // [64]  (32 per half)
#define OFF_HCAT (OFF_XS + 64)              // per half: [2*HP][BH]
#define HCAT_HALF (2 * HP * BH)
#define OFF_GSM  (OFF_HCAT + 2 * HCAT_HALF) // per half: [NPAIR][GPITCH]
#define GSM_HALF (NPAIR * GPITCH)
#define SMEM_FLOATS (OFF_GSM + 2 * GSM_HALF)
#define SMEM_BYTES  (SMEM_FLOATS * (int)sizeof(float))   // ~214.4 KB

__device__ __forceinline__ float sigf(float v) {
    return __fdividef(1.0f, 1.0f + __expf(-v));
}
__device__ __forceinline__ float tanhfast(float v) {
    return __fdividef(2.0f, 1.0f + __expf(-2.0f * v)) - 1.0f;
}

__device__ __forceinline__ u64 pack2(float lo, float hi) {
    u64 r; asm("mov.b64 %0, {%1, %2};" : "=l"(r) : "f"(lo), "f"(hi)); return r;
}
__device__ __forceinline__ u64 fma2(u64 a, u64 b, u64 c) {
    u64 d; asm("fma.rn.f32x2 %0, %1, %2, %3;" : "=l"(d) : "l"(a), "l"(b), "l"(c)); return d;
}
__device__ __forceinline__ u64 add2(u64 a, u64 b) {
    u64 d; asm("add.rn.f32x2 %0, %1, %2;" : "=l"(d) : "l"(a), "l"(b)); return d;
}

__device__ __forceinline__ void half_bar(int half) {
    asm volatile("bar.sync %0, 128;" :: "r"(half + 1) : "memory");
}

// Register-tiled packed GEMM over one half:
// acc{A,B}[13] (f32x2 over col pairs) += hcat(K x 32) * W(K x 208)
// Thread tile: batch rows (b0, b0+1), cols j0..j0+25 as 13 pairs.
template <int K>
__device__ __forceinline__ void gemm_tile2(const float* __restrict__ W,
                                           const float* __restrict__ hc,
                                           int b0, int j0,
                                           u64 accA[13], u64 accB[13]) {
#pragma unroll
    for (int c = 0; c < 13; c++) { accA[c] = 0ull; accB[c] = 0ull; }
#pragma unroll 4
    for (int k = 0; k < K; k++) {
        float2 hv = *reinterpret_cast<const float2*>(hc + k * BH + b0);
        u64 ha = pack2(hv.x, hv.x);
        u64 hb = pack2(hv.y, hv.y);
        const u64* wr = reinterpret_cast<const u64*>(W + k * GP + j0);
#pragma unroll
        for (int c = 0; c < 13; c++) {
            u64 w = wr[c];
            accA[c] = fma2(ha, w, accA[c]);
            accB[c] = fma2(hb, w, accB[c]);
        }
    }
}

extern __shared__ float smf[];

__global__ __launch_bounds__(NTH, 1)
void lstm_rnn_kernel(const float* __restrict__ x,
                     const float* __restrict__ Wih1, const float* __restrict__ Whh1,
                     const float* __restrict__ bih1, const float* __restrict__ bhh1,
                     const float* __restrict__ Wih2, const float* __restrict__ Whh2,
                     const float* __restrict__ bih2, const float* __restrict__ bhh2,
                     const float* __restrict__ Wlin, const float* __restrict__ blin_p,
                     float* __restrict__ out) {
    float* W1   = smf + OFF_W1;
    float* W2   = smf + OFF_W2;
    float* wx   = smf + OFF_WX;
    float* bs1  = smf + OFF_BS1;
    float* bs2  = smf + OFF_BS2;
    float* wlin = smf + OFF_WLIN;

    const int t    = threadIdx.x;
    const int half = t >> 7;          // 0 or 1
    const int tl   = t & 127;         // lane within half
    const int bbase = blockIdx.x * BB + half * BH;

    float* xs   = smf + OFF_XS   + half * BH;
    float* hcat = smf + OFF_HCAT + half * HCAT_HALF;
    float* gsm  = smf + OFF_GSM  + half * GSM_HALF;

    // ---- one-time init: transpose + pad weights into SMEM (all 256 threads) ----
    for (int idx = t; idx < HP * GP; idx += NTH) {
        int k = idx / GP, gp = idx % GP;
        int g = gp / HP, j = gp % HP;
        W1[idx] = (j < H_ && k < H_) ? Whh1[(g * H_ + j) * H_ + k] : 0.f;
    }
    for (int idx = t; idx < 2 * HP * GP; idx += NTH) {
        int k = idx / GP, gp = idx % GP;
        int g = gp / HP, j = gp % HP;
        float v = 0.f;
        if (j < H_) {
            if (k < H_)                      v = Wih2[(g * H_ + j) * H_ + k];
            else if (k >= HP && k < HP + H_) v = Whh2[(g * H_ + j) * H_ + (k - HP)];
        }
        W2[idx] = v;
    }
    for (int gp = t; gp < GP; gp += NTH) {
        int g = gp / HP, j = gp % HP;
        if (j < H_) {
            wx[gp]  = Wih1[g * H_ + j];
            bs1[gp] = bih1[g * H_ + j] + bhh1[g * H_ + j];
            bs2[gp] = bih2[g * H_ + j] + bhh2[g * H_ + j];
        } else {
            wx[gp] = 0.f; bs1[gp] = 0.f; bs2[gp] = 0.f;
        }
    }
    if (t < 64) wlin[t] = (t < H_) ? Wlin[t] : 0.f;
    for (int idx = t; idx < 2 * HCAT_HALF; idx += NTH) (smf + OFF_HCAT)[idx] = 0.f;
    const float blin = blin_p[0];

    // GEMM tile coordinates (per half)
    const int bg = tl >> 3;            // 0..15
    const int b0 = bg * 2;             // batch rows b0, b0+1
    const int j0 = (tl & 7) * 26;      // 13 col pairs starting at j0 (even)
    const int p0 = j0 >> 1;

    // Elementwise coordinates (per half): thread owns batch row `be`, j = jb + 4i
    const int be = tl & 31;
    const int jb = tl >> 5;            // 0..3

    float c1r[13], c2r[13];
#pragma unroll
    for (int i = 0; i < 13; i++) { c1r[i] = 0.f; c2r[i] = 0.f; }

    float xnext = (tl < BH) ? x[(size_t)(bbase + tl) * T_] : 0.f;

    __syncthreads();

    for (int step = 0; step < T_; ++step) {
        if (tl < BH) xs[tl] = xnext;
        half_bar(half);
        if (tl < BH && step + 1 < T_)
            xnext = __ldg(&x[(size_t)(bbase + tl) * T_ + step + 1]);

        // ---- layer-1 GEMM: gates1 = h1 @ Whh1^T (+ x*wx + bias) ----
        {
            u64 accA[13], accB[13];
            gemm_tile2<HP>(W1, hcat, b0, j0, accA, accB);
            u64 xA = pack2(xs[b0], xs[b0]);
            u64 xB = pack2(xs[b0 + 1], xs[b0 + 1]);
#pragma unroll
            for (int c = 0; c < 13; c++) {
                int gp = j0 + 2 * c;
                u64 bp  = *reinterpret_cast<const u64*>(bs1 + gp);
                u64 wxp = *reinterpret_cast<const u64*>(wx + gp);
                u64 vA = fma2(xA, wxp, add2(accA[c], bp));
                u64 vB = fma2(xB, wxp, add2(accB[c], bp));
                float* row = gsm + (p0 + c) * GPITCH;
                *reinterpret_cast<u64*>(row + b0 * 2)       = vA;
                *reinterpret_cast<u64*>(row + (b0 + 1) * 2) = vB;
            }
        }
        half_bar(half);

        // ---- layer-1 elementwise (h1 -> hcat rows 0..51) ----
#pragma unroll
        for (int i = 0; i < 13; i++) {
            int j = jb + 4 * i;
            int g0 = (0 * HP + j), g1 = (1 * HP + j), g2 = (2 * HP + j), g3 = (3 * HP + j);
            float ig = gsm[(g0 >> 1) * GPITCH + be * 2 + (g0 & 1)];
            float fg = gsm[(g1 >> 1) * GPITCH + be * 2 + (g1 & 1)];
            float gg = gsm[(g2 >> 1) * GPITCH + be * 2 + (g2 & 1)];
            float og = gsm[(g3 >> 1) * GPITCH + be * 2 + (g3 & 1)];
            float ia = sigf(ig), fa = sigf(fg), ga = tanhfast(gg), oa = sigf(og);
            float c = fmaf(fa, c1r[i], ia * ga);
            c1r[i] = c;
            hcat[j * BH + be] = oa * tanhfast(c);
        }
        half_bar(half);

        // ---- layer-2 GEMM: gates2 = [h1;h2] @ [Wih2;Whh2]^T (+ bias) ----
        {
            u64 accA[13], accB[13];
            gemm_tile2<2 * HP>(W2, hcat, b0, j0, accA, accB);
#pragma unroll
            for (int c = 0; c < 13; c++) {
                int gp = j0 + 2 * c;
                u64 bp = *reinterpret_cast<const u64*>(bs2 + gp);
                float* row = gsm + (p0 + c) * GPITCH;
                *reinterpret_cast<u64*>(row + b0 * 2)       = add2(accA[c], bp);
                *reinterpret_cast<u64*>(row + (b0 + 1) * 2) = add2(accB[c], bp);
            }
        }
        half_bar(half);

        // ---- layer-2 elementwise (h2 -> hcat rows 52..103) ----
#pragma unroll
        for (int i = 0; i < 13; i++) {
            int j = jb + 4 * i;
            int g0 = (0 * HP + j), g1 = (1 * HP + j), g2 = (2 * HP + j), g3 = (3 * HP + j);
            float ig = gsm[(g0 >> 1) * GPITCH + be * 2 + (g0 & 1)];
            float fg = gsm[(g1 >> 1) * GPITCH + be * 2 + (g1 & 1)];
            float gg = gsm[(g2 >> 1) * GPITCH + be * 2 + (g2 & 1)];
            float og = gsm[(g3 >> 1) * GPITCH + be * 2 + (g3 & 1)];
            float ia = sigf(ig), fa = sigf(fg), ga = tanhfast(gg), oa = sigf(og);
            float c = fmaf(fa, c2r[i], ia * ga);
            c2r[i] = c;
            hcat[(HP + j) * BH + be] = oa * tanhfast(c);
        }
        half_bar(half);

        // ---- output projection: y[b] = h2 . Wlin + blin ----
        if (tl < BH) {
            float y = blin;
#pragma unroll
            for (int j = 0; j < H_; j++)
                y = fmaf(hcat[(HP + j) * BH + tl], wlin[j], y);
            out[(size_t)(bbase + tl) * T_ + step] = y;
        }
        // loop-top half_bar separates out-proj hcat reads from next write phases
    }
}

extern "C" void kernel_launch(void* const* d_in, const int* in_sizes, int n_in,
                              void* d_out, int out_size) {
    (void)in_sizes; (void)n_in; (void)out_size;
    const float* x    = (const float*)d_in[0];
    const float* Wih1 = (const float*)d_in[1];
    const float* Whh1 = (const float*)d_in[2];
    const float* bih1 = (const float*)d_in[3];
    const float* bhh1 = (const float*)d_in[4];
    const float* Wih2 = (const float*)d_in[5];
    const float* Whh2 = (const float*)d_in[6];
    const float* bih2 = (const float*)d_in[7];
    const float* bhh2 = (const float*)d_in[8];
    const float* Wlin = (const float*)d_in[9];
    const float* blin = (const float*)d_in[10];
    float* out = (float*)d_out;

    cudaFuncSetAttribute(lstm_rnn_kernel,
                         cudaFuncAttributeMaxDynamicSharedMemorySize, SMEM_BYTES);

    lstm_rnn_kernel<<<NBLK, NTH, SMEM_BYTES>>>(x, Wih1, Whh1, bih1, bhh1,
                                               Wih2, Whh2, bih2, bhh2,
                                               Wlin, blin, out);
}